// round 10
// baseline (speedup 1.0000x reference)
#include <cuda_runtime.h>
#include <cuda_fp16.h>

// Problem constants
#define Bb    4
#define Tt    16
#define Hh    64
#define Ww    64
#define Cc    256
#define NCLS  512
#define TAPS  27
#define WCHUNK 32
#define WOFF_BYTES  (TAPS * Cc * 2)   // 13824 B per class in main table
#define CWOFF_BYTES (9 * Cc * 2)      // 4608 B per class in combined tables

// Transposed fp16 weight table: [class][tap][channel]
__device__ __align__(16) __half g_wt[NCLS * TAPS * Cc];
// Temporal-edge combined tables: [class][dh*3+dw][channel]
//   g_wc01  = W(dt=0)+W(dt=1)          (for t==1, clamped cell t'=0)
//   g_wc012 = W(dt=0)+W(dt=1)+W(dt=2)  (for t==0)
__device__ __align__(16) __half g_wc01 [NCLS * 9 * Cc];
__device__ __align__(16) __half g_wc012[NCLS * 9 * Cc];

// ---------------------------------------------------------------------------
// Kernel A: transpose + fp16 convert + edge-combined tables.
// R10: one block per class; write side packs 8 fp16/thread -> STG.128
// (R9 wrote scalar 2B stores, ~3x the write wavefronts).
// ---------------------------------------------------------------------------
__global__ void __launch_bounds__(256) wt_transpose_kernel(const float* __restrict__ w)
{
    __shared__ float s[256 * 27 + 1];   // [c][k], stride 27 (odd) -> conflict-free
    const int n   = blockIdx.x;         // class
    const int tid = threadIdx.x;

    // Read: thread i covers consecutive (c,k); per channel a 108B contiguous run.
    for (int i = tid; i < 256 * 27; i += 256) {
        int c = i / 27, k = i % 27;
        s[i] = w[(size_t)c * (NCLS * TAPS) + (size_t)n * TAPS + k];
    }
    __syncthreads();

    // Write g_wt: unit = 8 consecutive channels of one tap row -> STG.128.
    for (int j = tid; j < 27 * 32; j += 256) {
        int k  = j >> 5;
        int c8 = (j & 31) * 8;
        __half2 h0 = __floats2half2_rn(s[(c8+0)*27+k], s[(c8+1)*27+k]);
        __half2 h1 = __floats2half2_rn(s[(c8+2)*27+k], s[(c8+3)*27+k]);
        __half2 h2 = __floats2half2_rn(s[(c8+4)*27+k], s[(c8+5)*27+k]);
        __half2 h3 = __floats2half2_rn(s[(c8+6)*27+k], s[(c8+7)*27+k]);
        uint4 pk;
        pk.x = *reinterpret_cast<unsigned*>(&h0);
        pk.y = *reinterpret_cast<unsigned*>(&h1);
        pk.z = *reinterpret_cast<unsigned*>(&h2);
        pk.w = *reinterpret_cast<unsigned*>(&h3);
        *reinterpret_cast<uint4*>(&g_wt[(n * TAPS + k) * Cc + c8]) = pk;
    }
    // Combined temporal-edge tables (fp32 sums, single fp16 rounding).
    for (int j = tid; j < 9 * 32; j += 256) {
        int jt = j >> 5;                // dh*3+dw
        int c8 = (j & 31) * 8;
        float v01[8], v012[8];
        #pragma unroll
        for (int e = 0; e < 8; e++) {
            float w0 = s[(c8+e)*27 + jt];
            float w1 = s[(c8+e)*27 + 9 + jt];
            float w2 = s[(c8+e)*27 + 18 + jt];
            v01[e]  = w0 + w1;
            v012[e] = w0 + w1 + w2;
        }
        uint4 p1, p2;
        __half2 a, bq;
        a = __floats2half2_rn(v01[0], v01[1]);  p1.x = *reinterpret_cast<unsigned*>(&a);
        a = __floats2half2_rn(v01[2], v01[3]);  p1.y = *reinterpret_cast<unsigned*>(&a);
        a = __floats2half2_rn(v01[4], v01[5]);  p1.z = *reinterpret_cast<unsigned*>(&a);
        a = __floats2half2_rn(v01[6], v01[7]);  p1.w = *reinterpret_cast<unsigned*>(&a);
        bq = __floats2half2_rn(v012[0], v012[1]); p2.x = *reinterpret_cast<unsigned*>(&bq);
        bq = __floats2half2_rn(v012[2], v012[3]); p2.y = *reinterpret_cast<unsigned*>(&bq);
        bq = __floats2half2_rn(v012[4], v012[5]); p2.z = *reinterpret_cast<unsigned*>(&bq);
        bq = __floats2half2_rn(v012[6], v012[7]); p2.w = *reinterpret_cast<unsigned*>(&bq);
        *reinterpret_cast<uint4*>(&g_wc01 [(n * 9 + jt) * Cc + c8]) = p1;
        *reinterpret_cast<uint4*>(&g_wc012[(n * 9 + jt) * Cc + c8]) = p2;
    }
}

// ---------------------------------------------------------------------------
// Kernel B: gather-accumulate (R9 + full pass unroll @ occ 4).
// R10 change: pass loop fully unrolled, __launch_bounds__(256,4) (64-reg cap).
// Rationale: each rolled pass had a dependent LDS->shuffle->load-burst head
// and a return-drain tail; unrolling lets the compiler hoist all 4 class
// loads and overlap pass p+1's load burst with pass p's accumulation.
// R3 already showed occ-4 runs as fast as occ-5 here.
// ---------------------------------------------------------------------------
__global__ void __launch_bounds__(256, 4) onehot_conv_kernel(
    const int*   __restrict__ indices,
    const float* __restrict__ bias,
    float*       __restrict__ out)
{
    // [w][32 x 16B units]; each unit = 8 channels in fp16. 16KB.
    __shared__ __align__(16) uint4 s_stage[WCHUNK * 32];
    __shared__ int s_off[9 * 34];                 // raw classes, halo'd in w

    const int bx   = blockIdx.x;
    const int wblk = bx & 1;
    const int h    = (bx >> 1) & 63;
    const int t    = (bx >> 7) & 15;
    const int b    = bx >> 11;
    const int w0   = wblk * WCHUNK;
    const int tid  = threadIdx.x;

    // Halo of classes: 9 (dt,dh) rows x 34 w, edge-clamped.
    for (int i = tid; i < 9 * 34; i += 256) {
        int r  = i / 34, j = i % 34;
        int dt = r / 3,  dh = r % 3;
        int st = t + dt - 2; if (st < 0) st = 0;
        int sh = h + dh - 1; if (sh < 0) sh = 0; if (sh > Hh - 1) sh = Hh - 1;
        int gw = w0 + j - 1; if (gw < 0) gw = 0; if (gw > Ww - 1) gw = Ww - 1;
        s_off[i] = indices[((b * Tt + st) * Hh + sh) * Ww + gw];
    }
    __syncthreads();

    const int warp = tid >> 5;
    const int lane = tid & 31;
    const int kl   = lane < 27 ? lane : 26;     // lane -> tap (guarded)
    const int rIdx = (kl / 3) * 34 + (kl % 3);  // row part of s_off index

    const char* baseW  = reinterpret_cast<const char*>(g_wt)    + lane * 16; // 8 ch, fp16x8
    const char* baseC1 = reinterpret_cast<const char*>(g_wc01)  + lane * 16;
    const char* baseC2 = reinterpret_cast<const char*>(g_wc012) + lane * 16;

    const float4 bz0 = *reinterpret_cast<const float4*>(bias + 8 * lane);
    const float4 bz1 = *reinterpret_cast<const float4*>(bias + 8 * lane + 4);

    #pragma unroll
    for (int p = 0; p < 4; p++) {
        const int w_l = p * 8 + warp;
        const int cls = s_off[rIdx + w_l];      // this lane's tap-class
        const int moW = cls * WOFF_BYTES;       // offset into g_wt
        const int moC = cls * CWOFF_BYTES;      // offset into combined tables

        float4 a0 = bz0, a1 = bz1;

        if (t >= 2) {
            // 13 pairs + 1 single from the full table.
            #pragma unroll
            for (int k = 0; k < 26; k += 2) {
                const int o0 = __shfl_sync(0xffffffffu, moW, k);
                const int o1 = __shfl_sync(0xffffffffu, moW, k + 1);
                uint4 u0 = *reinterpret_cast<const uint4*>(baseW + o0 + k * 512);
                uint4 u1 = *reinterpret_cast<const uint4*>(baseW + o1 + (k + 1) * 512);
                __half2 s0 = __hadd2(*reinterpret_cast<__half2*>(&u0.x), *reinterpret_cast<__half2*>(&u1.x));
                __half2 s1 = __hadd2(*reinterpret_cast<__half2*>(&u0.y), *reinterpret_cast<__half2*>(&u1.y));
                __half2 s2 = __hadd2(*reinterpret_cast<__half2*>(&u0.z), *reinterpret_cast<__half2*>(&u1.z));
                __half2 s3 = __hadd2(*reinterpret_cast<__half2*>(&u0.w), *reinterpret_cast<__half2*>(&u1.w));
                float2 f;
                f = __half22float2(s0); a0.x += f.x; a0.y += f.y;
                f = __half22float2(s1); a0.z += f.x; a0.w += f.y;
                f = __half22float2(s2); a1.x += f.x; a1.y += f.y;
                f = __half22float2(s3); a1.z += f.x; a1.w += f.y;
            }
            const int o = __shfl_sync(0xffffffffu, moW, 26);
            uint4 u = *reinterpret_cast<const uint4*>(baseW + o + 26 * 512);
            float2 f;
            f = __half22float2(*reinterpret_cast<__half2*>(&u.x)); a0.x += f.x; a0.y += f.y;
            f = __half22float2(*reinterpret_cast<__half2*>(&u.y)); a0.z += f.x; a0.w += f.y;
            f = __half22float2(*reinterpret_cast<__half2*>(&u.z)); a1.x += f.x; a1.y += f.y;
            f = __half22float2(*reinterpret_cast<__half2*>(&u.w)); a1.z += f.x; a1.w += f.y;
        } else if (t == 1) {
            // 9 pairs: (Wc01 row j, dt=0 cells) + (W row 18+j, dt=2 cells).
            #pragma unroll
            for (int j = 0; j < 9; j++) {
                const int oc = __shfl_sync(0xffffffffu, moC, j);
                const int ow = __shfl_sync(0xffffffffu, moW, 18 + j);
                uint4 u0 = *reinterpret_cast<const uint4*>(baseC1 + oc + j * 512);
                uint4 u1 = *reinterpret_cast<const uint4*>(baseW + ow + (18 + j) * 512);
                __half2 s0 = __hadd2(*reinterpret_cast<__half2*>(&u0.x), *reinterpret_cast<__half2*>(&u1.x));
                __half2 s1 = __hadd2(*reinterpret_cast<__half2*>(&u0.y), *reinterpret_cast<__half2*>(&u1.y));
                __half2 s2 = __hadd2(*reinterpret_cast<__half2*>(&u0.z), *reinterpret_cast<__half2*>(&u1.z));
                __half2 s3 = __hadd2(*reinterpret_cast<__half2*>(&u0.w), *reinterpret_cast<__half2*>(&u1.w));
                float2 f;
                f = __half22float2(s0); a0.x += f.x; a0.y += f.y;
                f = __half22float2(s1); a0.z += f.x; a0.w += f.y;
                f = __half22float2(s2); a1.x += f.x; a1.y += f.y;
                f = __half22float2(s3); a1.z += f.x; a1.w += f.y;
            }
        } else {
            // t == 0: 9 gathers from Wc012 (4 pairs + 1 single).
            #pragma unroll
            for (int j = 0; j < 8; j += 2) {
                const int o0 = __shfl_sync(0xffffffffu, moC, j);
                const int o1 = __shfl_sync(0xffffffffu, moC, j + 1);
                uint4 u0 = *reinterpret_cast<const uint4*>(baseC2 + o0 + j * 512);
                uint4 u1 = *reinterpret_cast<const uint4*>(baseC2 + o1 + (j + 1) * 512);
                __half2 s0 = __hadd2(*reinterpret_cast<__half2*>(&u0.x), *reinterpret_cast<__half2*>(&u1.x));
                __half2 s1 = __hadd2(*reinterpret_cast<__half2*>(&u0.y), *reinterpret_cast<__half2*>(&u1.y));
                __half2 s2 = __hadd2(*reinterpret_cast<__half2*>(&u0.z), *reinterpret_cast<__half2*>(&u1.z));
                __half2 s3 = __hadd2(*reinterpret_cast<__half2*>(&u0.w), *reinterpret_cast<__half2*>(&u1.w));
                float2 f;
                f = __half22float2(s0); a0.x += f.x; a0.y += f.y;
                f = __half22float2(s1); a0.z += f.x; a0.w += f.y;
                f = __half22float2(s2); a1.x += f.x; a1.y += f.y;
                f = __half22float2(s3); a1.z += f.x; a1.w += f.y;
            }
            const int o = __shfl_sync(0xffffffffu, moC, 8);
            uint4 u = *reinterpret_cast<const uint4*>(baseC2 + o + 8 * 512);
            float2 f;
            f = __half22float2(*reinterpret_cast<__half2*>(&u.x)); a0.x += f.x; a0.y += f.y;
            f = __half22float2(*reinterpret_cast<__half2*>(&u.y)); a0.z += f.x; a0.w += f.y;
            f = __half22float2(*reinterpret_cast<__half2*>(&u.z)); a1.x += f.x; a1.y += f.y;
            f = __half22float2(*reinterpret_cast<__half2*>(&u.w)); a1.z += f.x; a1.w += f.y;
        }

        // Pack 8 channels to fp16 and store one 16B unit, XOR-swizzled by w.
        __half2 h0 = __floats2half2_rn(a0.x, a0.y);
        __half2 h1 = __floats2half2_rn(a0.z, a0.w);
        __half2 h2 = __floats2half2_rn(a1.x, a1.y);
        __half2 h3 = __floats2half2_rn(a1.z, a1.w);
        uint4 pk;
        pk.x = *reinterpret_cast<unsigned*>(&h0);
        pk.y = *reinterpret_cast<unsigned*>(&h1);
        pk.z = *reinterpret_cast<unsigned*>(&h2);
        pk.w = *reinterpret_cast<unsigned*>(&h3);
        s_stage[w_l * 32 + (lane ^ (w_l & 31))] = pk;
    }
    __syncthreads();

    // Read-back: logical unit uu (8 channels) at phys uu^(lane&31); lane = w.
    const size_t THW   = (size_t)Tt * Hh * Ww;
    const size_t obase = (size_t)b * Cc * THW + (size_t)t * (Hh * Ww) + (size_t)h * Ww + w0;
    #pragma unroll
    for (int uu = warp; uu < 32; uu += 8) {
        uint4 pk = s_stage[lane * 32 + (uu ^ lane)];
        float2 f0 = __half22float2(*reinterpret_cast<__half2*>(&pk.x));
        float2 f1 = __half22float2(*reinterpret_cast<__half2*>(&pk.y));
        float2 f2 = __half22float2(*reinterpret_cast<__half2*>(&pk.z));
        float2 f3 = __half22float2(*reinterpret_cast<__half2*>(&pk.w));
        const int c = uu * 8;
        out[obase + (size_t)(c + 0) * THW + lane] = f0.x;
        out[obase + (size_t)(c + 1) * THW + lane] = f0.y;
        out[obase + (size_t)(c + 2) * THW + lane] = f1.x;
        out[obase + (size_t)(c + 3) * THW + lane] = f1.y;
        out[obase + (size_t)(c + 4) * THW + lane] = f2.x;
        out[obase + (size_t)(c + 5) * THW + lane] = f2.y;
        out[obase + (size_t)(c + 6) * THW + lane] = f3.x;
        out[obase + (size_t)(c + 7) * THW + lane] = f3.y;
    }
}

// ---------------------------------------------------------------------------
extern "C" void kernel_launch(void* const* d_in, const int* in_sizes, int n_in,
                              void* d_out, int out_size)
{
    const int*   indices = (const int*)  d_in[0];
    const float* weight  = (const float*)d_in[1];
    const float* bias    = (const float*)d_in[2];
    float*       out     = (float*)d_out;

    wt_transpose_kernel<<<NCLS, 256>>>(weight);

    const int grid = Bb * Tt * Hh * (Ww / WCHUNK);   // 8192
    onehot_conv_kernel<<<grid, 256>>>(indices, bias, out);
}

// round 11
// speedup vs baseline: 1.0486x; 1.0486x over previous
#include <cuda_runtime.h>
#include <cuda_fp16.h>

// Problem constants
#define Bb    4
#define Tt    16
#define Hh    64
#define Ww    64
#define Cc    256
#define NCLS  512
#define TAPS  27
#define NK    (NCLS * TAPS)           // 13824
#define WCHUNK 32
#define WOFF_BYTES  (TAPS * Cc * 2)   // 13824 B per class in main table
#define CWOFF_BYTES (9 * Cc * 2)      // 4608 B per class in combined tables

// Transposed fp16 weight table: [class][tap][channel]
__device__ __align__(16) __half g_wt[NK * Cc];
// Temporal-edge combined tables: [class][dh*3+dw][channel]
//   g_wc01  = W(dt=0)+W(dt=1)          (for t==1, clamped cell t'=0)
//   g_wc012 = W(dt=0)+W(dt=1)+W(dt=2)  (for t==0)
__device__ __align__(16) __half g_wc01 [NCLS * 9 * Cc];
__device__ __align__(16) __half g_wc012[NCLS * 9 * Cc];

// ---------------------------------------------------------------------------
// Kernel A1: plain tiled 2D transpose, 256 x 13824 fp32 -> 13824 x 256 fp16.
// 32x32 tiles via smem (stride 33). Reads 128B-coalesced, writes 64B-coalesced.
// grid = (NK/32, Cc/32) = (432, 8).
// ---------------------------------------------------------------------------
__global__ void __launch_bounds__(256) wt_transpose_kernel(const float* __restrict__ w)
{
    __shared__ float s[32][33];
    const int nk0  = blockIdx.x * 32;
    const int c0   = blockIdx.y * 32;
    const int lane = threadIdx.x & 31;
    const int wrp  = threadIdx.x >> 5;

    #pragma unroll
    for (int r = 0; r < 4; r++) {
        int c = wrp * 4 + r;
        s[c][lane] = w[(size_t)(c0 + c) * NK + nk0 + lane];
    }
    __syncthreads();
    #pragma unroll
    for (int r = 0; r < 4; r++) {
        int nkr = wrp * 4 + r;
        g_wt[(size_t)(nk0 + nkr) * Cc + c0 + lane] = __float2half_rn(s[lane][nkr]);
    }
}

// ---------------------------------------------------------------------------
// Kernel A2: build combined temporal-edge tables from g_wt.
// Fully coalesced half2 reads/writes. grid = NCLS*9*128/256 = 2304.
// ---------------------------------------------------------------------------
__global__ void __launch_bounds__(256) wt_combine_kernel()
{
    const int idx = blockIdx.x * 256 + threadIdx.x;   // over NCLS*9*128
    const int c2  = idx & 127;
    const int jt  = (idx >> 7) % 9;
    const int n   = idx / (9 * 128);

    const __half2* wt2 = reinterpret_cast<const __half2*>(g_wt);
    __half2 h0 = wt2[(n * 27 + jt)      * 128 + c2];
    __half2 h1 = wt2[(n * 27 + 9 + jt)  * 128 + c2];
    __half2 h2 = wt2[(n * 27 + 18 + jt) * 128 + c2];
    float2 f0 = __half22float2(h0), f1 = __half22float2(h1), f2 = __half22float2(h2);
    float sx01 = f0.x + f1.x, sy01 = f0.y + f1.y;
    reinterpret_cast<__half2*>(g_wc01)[(n * 9 + jt) * 128 + c2]  = __floats2half2_rn(sx01, sy01);
    reinterpret_cast<__half2*>(g_wc012)[(n * 9 + jt) * 128 + c2] = __floats2half2_rn(sx01 + f2.x, sy01 + f2.y);
}

// ---------------------------------------------------------------------------
// Kernel B: gather-accumulate (unchanged from R10: LDG.128, pairwise HADD2,
// fp16 smem staging, full pass unroll @ occ 4, temporal-edge combined taps).
// ---------------------------------------------------------------------------
__global__ void __launch_bounds__(256, 4) onehot_conv_kernel(
    const int*   __restrict__ indices,
    const float* __restrict__ bias,
    float*       __restrict__ out)
{
    // [w][32 x 16B units]; each unit = 8 channels in fp16. 16KB.
    __shared__ __align__(16) uint4 s_stage[WCHUNK * 32];
    __shared__ int s_off[9 * 34];                 // raw classes, halo'd in w

    const int bx   = blockIdx.x;
    const int wblk = bx & 1;
    const int h    = (bx >> 1) & 63;
    const int t    = (bx >> 7) & 15;
    const int b    = bx >> 11;
    const int w0   = wblk * WCHUNK;
    const int tid  = threadIdx.x;

    // Halo of classes: 9 (dt,dh) rows x 34 w, edge-clamped.
    for (int i = tid; i < 9 * 34; i += 256) {
        int r  = i / 34, j = i % 34;
        int dt = r / 3,  dh = r % 3;
        int st = t + dt - 2; if (st < 0) st = 0;
        int sh = h + dh - 1; if (sh < 0) sh = 0; if (sh > Hh - 1) sh = Hh - 1;
        int gw = w0 + j - 1; if (gw < 0) gw = 0; if (gw > Ww - 1) gw = Ww - 1;
        s_off[i] = indices[((b * Tt + st) * Hh + sh) * Ww + gw];
    }
    __syncthreads();

    const int warp = tid >> 5;
    const int lane = tid & 31;
    const int kl   = lane < 27 ? lane : 26;     // lane -> tap (guarded)
    const int rIdx = (kl / 3) * 34 + (kl % 3);  // row part of s_off index

    const char* baseW  = reinterpret_cast<const char*>(g_wt)    + lane * 16; // 8 ch, fp16x8
    const char* baseC1 = reinterpret_cast<const char*>(g_wc01)  + lane * 16;
    const char* baseC2 = reinterpret_cast<const char*>(g_wc012) + lane * 16;

    const float4 bz0 = *reinterpret_cast<const float4*>(bias + 8 * lane);
    const float4 bz1 = *reinterpret_cast<const float4*>(bias + 8 * lane + 4);

    #pragma unroll
    for (int p = 0; p < 4; p++) {
        const int w_l = p * 8 + warp;
        const int cls = s_off[rIdx + w_l];      // this lane's tap-class
        const int moW = cls * WOFF_BYTES;       // offset into g_wt
        const int moC = cls * CWOFF_BYTES;      // offset into combined tables

        float4 a0 = bz0, a1 = bz1;

        if (t >= 2) {
            // 13 pairs + 1 single from the full table.
            #pragma unroll
            for (int k = 0; k < 26; k += 2) {
                const int o0 = __shfl_sync(0xffffffffu, moW, k);
                const int o1 = __shfl_sync(0xffffffffu, moW, k + 1);
                uint4 u0 = *reinterpret_cast<const uint4*>(baseW + o0 + k * 512);
                uint4 u1 = *reinterpret_cast<const uint4*>(baseW + o1 + (k + 1) * 512);
                __half2 s0 = __hadd2(*reinterpret_cast<__half2*>(&u0.x), *reinterpret_cast<__half2*>(&u1.x));
                __half2 s1 = __hadd2(*reinterpret_cast<__half2*>(&u0.y), *reinterpret_cast<__half2*>(&u1.y));
                __half2 s2 = __hadd2(*reinterpret_cast<__half2*>(&u0.z), *reinterpret_cast<__half2*>(&u1.z));
                __half2 s3 = __hadd2(*reinterpret_cast<__half2*>(&u0.w), *reinterpret_cast<__half2*>(&u1.w));
                float2 f;
                f = __half22float2(s0); a0.x += f.x; a0.y += f.y;
                f = __half22float2(s1); a0.z += f.x; a0.w += f.y;
                f = __half22float2(s2); a1.x += f.x; a1.y += f.y;
                f = __half22float2(s3); a1.z += f.x; a1.w += f.y;
            }
            const int o = __shfl_sync(0xffffffffu, moW, 26);
            uint4 u = *reinterpret_cast<const uint4*>(baseW + o + 26 * 512);
            float2 f;
            f = __half22float2(*reinterpret_cast<__half2*>(&u.x)); a0.x += f.x; a0.y += f.y;
            f = __half22float2(*reinterpret_cast<__half2*>(&u.y)); a0.z += f.x; a0.w += f.y;
            f = __half22float2(*reinterpret_cast<__half2*>(&u.z)); a1.x += f.x; a1.y += f.y;
            f = __half22float2(*reinterpret_cast<__half2*>(&u.w)); a1.z += f.x; a1.w += f.y;
        } else if (t == 1) {
            // 9 pairs: (Wc01 row j, dt=0 cells) + (W row 18+j, dt=2 cells).
            #pragma unroll
            for (int j = 0; j < 9; j++) {
                const int oc = __shfl_sync(0xffffffffu, moC, j);
                const int ow = __shfl_sync(0xffffffffu, moW, 18 + j);
                uint4 u0 = *reinterpret_cast<const uint4*>(baseC1 + oc + j * 512);
                uint4 u1 = *reinterpret_cast<const uint4*>(baseW + ow + (18 + j) * 512);
                __half2 s0 = __hadd2(*reinterpret_cast<__half2*>(&u0.x), *reinterpret_cast<__half2*>(&u1.x));
                __half2 s1 = __hadd2(*reinterpret_cast<__half2*>(&u0.y), *reinterpret_cast<__half2*>(&u1.y));
                __half2 s2 = __hadd2(*reinterpret_cast<__half2*>(&u0.z), *reinterpret_cast<__half2*>(&u1.z));
                __half2 s3 = __hadd2(*reinterpret_cast<__half2*>(&u0.w), *reinterpret_cast<__half2*>(&u1.w));
                float2 f;
                f = __half22float2(s0); a0.x += f.x; a0.y += f.y;
                f = __half22float2(s1); a0.z += f.x; a0.w += f.y;
                f = __half22float2(s2); a1.x += f.x; a1.y += f.y;
                f = __half22float2(s3); a1.z += f.x; a1.w += f.y;
            }
        } else {
            // t == 0: 9 gathers from Wc012 (4 pairs + 1 single).
            #pragma unroll
            for (int j = 0; j < 8; j += 2) {
                const int o0 = __shfl_sync(0xffffffffu, moC, j);
                const int o1 = __shfl_sync(0xffffffffu, moC, j + 1);
                uint4 u0 = *reinterpret_cast<const uint4*>(baseC2 + o0 + j * 512);
                uint4 u1 = *reinterpret_cast<const uint4*>(baseC2 + o1 + (j + 1) * 512);
                __half2 s0 = __hadd2(*reinterpret_cast<__half2*>(&u0.x), *reinterpret_cast<__half2*>(&u1.x));
                __half2 s1 = __hadd2(*reinterpret_cast<__half2*>(&u0.y), *reinterpret_cast<__half2*>(&u1.y));
                __half2 s2 = __hadd2(*reinterpret_cast<__half2*>(&u0.z), *reinterpret_cast<__half2*>(&u1.z));
                __half2 s3 = __hadd2(*reinterpret_cast<__half2*>(&u0.w), *reinterpret_cast<__half2*>(&u1.w));
                float2 f;
                f = __half22float2(s0); a0.x += f.x; a0.y += f.y;
                f = __half22float2(s1); a0.z += f.x; a0.w += f.y;
                f = __half22float2(s2); a1.x += f.x; a1.y += f.y;
                f = __half22float2(s3); a1.z += f.x; a1.w += f.y;
            }
            const int o = __shfl_sync(0xffffffffu, moC, 8);
            uint4 u = *reinterpret_cast<const uint4*>(baseC2 + o + 8 * 512);
            float2 f;
            f = __half22float2(*reinterpret_cast<__half2*>(&u.x)); a0.x += f.x; a0.y += f.y;
            f = __half22float2(*reinterpret_cast<__half2*>(&u.y)); a0.z += f.x; a0.w += f.y;
            f = __half22float2(*reinterpret_cast<__half2*>(&u.z)); a1.x += f.x; a1.y += f.y;
            f = __half22float2(*reinterpret_cast<__half2*>(&u.w)); a1.z += f.x; a1.w += f.y;
        }

        // Pack 8 channels to fp16 and store one 16B unit, XOR-swizzled by w.
        __half2 h0 = __floats2half2_rn(a0.x, a0.y);
        __half2 h1 = __floats2half2_rn(a0.z, a0.w);
        __half2 h2 = __floats2half2_rn(a1.x, a1.y);
        __half2 h3 = __floats2half2_rn(a1.z, a1.w);
        uint4 pk;
        pk.x = *reinterpret_cast<unsigned*>(&h0);
        pk.y = *reinterpret_cast<unsigned*>(&h1);
        pk.z = *reinterpret_cast<unsigned*>(&h2);
        pk.w = *reinterpret_cast<unsigned*>(&h3);
        s_stage[w_l * 32 + (lane ^ (w_l & 31))] = pk;
    }
    __syncthreads();

    // Read-back: logical unit uu (8 channels) at phys uu^(lane&31); lane = w.
    const size_t THW   = (size_t)Tt * Hh * Ww;
    const size_t obase = (size_t)b * Cc * THW + (size_t)t * (Hh * Ww) + (size_t)h * Ww + w0;
    #pragma unroll
    for (int uu = warp; uu < 32; uu += 8) {
        uint4 pk = s_stage[lane * 32 + (uu ^ lane)];
        float2 f0 = __half22float2(*reinterpret_cast<__half2*>(&pk.x));
        float2 f1 = __half22float2(*reinterpret_cast<__half2*>(&pk.y));
        float2 f2 = __half22float2(*reinterpret_cast<__half2*>(&pk.z));
        float2 f3 = __half22float2(*reinterpret_cast<__half2*>(&pk.w));
        const int c = uu * 8;
        out[obase + (size_t)(c + 0) * THW + lane] = f0.x;
        out[obase + (size_t)(c + 1) * THW + lane] = f0.y;
        out[obase + (size_t)(c + 2) * THW + lane] = f1.x;
        out[obase + (size_t)(c + 3) * THW + lane] = f1.y;
        out[obase + (size_t)(c + 4) * THW + lane] = f2.x;
        out[obase + (size_t)(c + 5) * THW + lane] = f2.y;
        out[obase + (size_t)(c + 6) * THW + lane] = f3.x;
        out[obase + (size_t)(c + 7) * THW + lane] = f3.y;
    }
}

// ---------------------------------------------------------------------------
extern "C" void kernel_launch(void* const* d_in, const int* in_sizes, int n_in,
                              void* d_out, int out_size)
{
    const int*   indices = (const int*)  d_in[0];
    const float* weight  = (const float*)d_in[1];
    const float* bias    = (const float*)d_in[2];
    float*       out     = (float*)d_out;

    dim3 tgrid(NK / 32, Cc / 32);                  // (432, 8)
    wt_transpose_kernel<<<tgrid, 256>>>(weight);
    wt_combine_kernel<<<NCLS * 9 * 128 / 256, 256>>>();

    const int grid = Bb * Tt * Hh * (Ww / WCHUNK); // 8192
    onehot_conv_kernel<<<grid, 256>>>(indices, bias, out);
}